// round 5
// baseline (speedup 1.0000x reference)
#include <cuda_runtime.h>
#include <cuda_fp16.h>
#include <cstdint>

// Problem constants
#define NB      32
#define CDIM    256
#define HWN     4096
#define KCODES  1024
#define N_VEC   (NB * HWN)        // 131072
#define N_ZQ    (NB * CDIM * HWN) // 33554432

#define MARGIN  2.0e-3f           // ~5x realistic worst-case |d_fast - d_ref|

// GEMM tiling: CTA = 128 vectors x 128 codes, K in 4 chunks of 64
#define MT     128
#define NSLICE 128
#define NSL    (KCODES / NSLICE)  // 8 n-slices
#define KCH    64

// ---------------- static device scratch ----------------
__device__ __half g_zh[(size_t)N_VEC * CDIM];  // f16 z, [vec][dim]
__device__ float  g_zt[(size_t)N_VEC * CDIM];  // fp32 z, [vec][dim]
__device__ __half g_eh[KCODES * CDIM];         // f16 codebook [code][dim]
__device__ float  g_se[KCODES];                // ||e||^2
__device__ float  g_sz[N_VEC];                 // ||z||^2 (ref order)
__device__ float  g_hmin[N_VEC * NSL];
__device__ int    g_hcnt[N_VEC * NSL];
__device__ float  g_hd[N_VEC * NSL * 4];
__device__ int    g_hi[N_VEC * NSL * 4];
__device__ int    g_idx[N_VEC];
__device__ int    g_wl[N_VEC];
__device__ int    g_wl_cnt;
__device__ double g_loss;

// ---------------- helpers ----------------
__device__ __forceinline__ uint32_t smem_u32(const void* p) {
    uint32_t a;
    asm("{ .reg .u64 t; cvta.to.shared.u64 t, %1; cvt.u32.u64 %0, t; }"
        : "=r"(a) : "l"(p));
    return a;
}
#define SW128(x) ((uint32_t)(x) ^ ((((uint32_t)(x)) >> 3) & 0x70u))

__device__ __forceinline__ void ldsm4(uint32_t* r, uint32_t addr) {
    asm volatile("ldmatrix.sync.aligned.m8n8.x4.shared.b16 {%0,%1,%2,%3}, [%4];"
                 : "=r"(r[0]), "=r"(r[1]), "=r"(r[2]), "=r"(r[3]) : "r"(addr));
}
__device__ __forceinline__ void mma16816(float* c, const uint32_t* a,
                                         uint32_t b0, uint32_t b1) {
    asm volatile("mma.sync.aligned.m16n8k16.row.col.f32.f16.f16.f32 "
                 "{%0,%1,%2,%3}, {%4,%5,%6,%7}, {%8,%9}, {%0,%1,%2,%3};"
                 : "+f"(c[0]), "+f"(c[1]), "+f"(c[2]), "+f"(c[3])
                 : "r"(a[0]), "r"(a[1]), "r"(a[2]), "r"(a[3]), "r"(b0), "r"(b1));
}

// ---------------------------------------------------------------------------
// Codebook prep: f16 copy, ||e||^2, zero global accumulators.
// ---------------------------------------------------------------------------
__global__ void cb_prep_kernel(const float* __restrict__ cb) {
    int n = blockIdx.x, t = threadIdx.x;
    float v = cb[n * CDIM + t];
    g_eh[n * CDIM + t] = __float2half(v);
    __shared__ float red[256];
    red[t] = __fmul_rn(v, v);
    __syncthreads();
    for (int s = 128; s > 0; s >>= 1) {
        if (t < s) red[t] = __fadd_rn(red[t], red[t + s]);
        __syncthreads();
    }
    if (t == 0) {
        g_se[n] = red[0];
        if (n == 0) { g_loss = 0.0; g_wl_cnt = 0; }
    }
}

// ---------------------------------------------------------------------------
// z prep: transpose [B,C,HW] -> [vec][dim] in fp32 (z_t) and f16 (zh).
// ---------------------------------------------------------------------------
__global__ void zprep_kernel(const float* __restrict__ z) {
    __shared__ float t[64][133];
    int tid = threadIdx.x;
    int b = blockIdx.z, c0 = blockIdx.y * 64, hw0 = blockIdx.x * 128;
    const float* src = z + ((size_t)b * CDIM + c0) * HWN + hw0;
#pragma unroll
    for (int it = 0; it < 32; it++) {
        int idx = it * 256 + tid;
        int cc = idx >> 7, h = idx & 127;
        t[cc][h] = src[(size_t)cc * HWN + h];
    }
    __syncthreads();
#pragma unroll
    for (int it = 0; it < 32; it++) {
        int idx = it * 256 + tid;
        int h = idx >> 6, cc = idx & 63;
        size_t o = (size_t)(b * HWN + hw0 + h) * CDIM + c0 + cc;
        float val = t[cc][h];
        g_zt[o] = val;
        g_zh[o] = __float2half(val);
    }
}

// ---------------------------------------------------------------------------
// ||z||^2 in reference order (serial ascending, unfused).
// ---------------------------------------------------------------------------
__global__ void sz_kernel(const float* __restrict__ z) {
    int v  = blockIdx.x * blockDim.x + threadIdx.x;
    int b  = v >> 12, hw = v & (HWN - 1);
    const float* p = z + (size_t)b * CDIM * HWN + hw;
    float acc = 0.0f;
#pragma unroll 8
    for (int c = 0; c < CDIM; c++) {
        float x = __ldg(p + (size_t)c * HWN);
        acc = __fadd_rn(acc, __fmul_rn(x, x));
    }
    g_sz[v] = acc;
}

// ---------------------------------------------------------------------------
// HMMA prefilter GEMM. Grid (1024, 8): 128 vecs x 128 codes per CTA.
// 8 warps (4m x 2n), warp tile 32x64, mma.m16n8k16 f16 -> fp32.
// Epilogue: scan dists, online min + 4 margin-candidate slots per row.
// ---------------------------------------------------------------------------
#define OFF_SE   68096                 // after dist region 128*133*4
#define OFF_CD   68608
#define OFF_CI   70656
#define SMEM_TOT 72704

__global__ void __launch_bounds__(256, 1)
vq_gemm_kernel() {
    extern __shared__ __align__(1024) char sm[];
    const uint32_t sb = smem_u32(sm);
    const int tid = threadIdx.x;
    const int wid = tid >> 5, lane = tid & 31;
    const int wm = wid >> 1, wn = wid & 1;
    const int m0 = blockIdx.x * MT;
    const int n0 = blockIdx.y * NSLICE;

    // se slice
    if (tid < NSLICE) ((float*)(sm + OFF_SE))[tid] = g_se[n0 + tid];

    float acc[2][8][4];
#pragma unroll
    for (int a = 0; a < 2; a++)
#pragma unroll
        for (int b = 0; b < 8; b++)
#pragma unroll
            for (int c = 0; c < 4; c++) acc[a][b][c] = 0.0f;

    // double-buffered A/B chunks: buf s at sm + s*32768, A 16KB then B 16KB
    auto load_chunk = [&](int kc) {
        const int s = kc & 1;
        const int kc0 = kc * KCH;
#pragma unroll
        for (int it = 0; it < 4; it++) {
            int idx = tid + it * 256;
            int r = idx >> 3, c8 = idx & 7;
            uint32_t off = SW128(r * 128 + c8 * 16);
            uint4 va = *(const uint4*)(g_zh + (size_t)(m0 + r) * CDIM + kc0 + c8 * 8);
            *(uint4*)(sm + s * 32768 + off) = va;
            uint4 vb = *(const uint4*)(g_eh + (size_t)(n0 + r) * CDIM + kc0 + c8 * 8);
            *(uint4*)(sm + s * 32768 + 16384 + off) = vb;
        }
    };

    const int q = lane >> 3, lr = lane & 7;
    const int arow = wm * 32 + ((q & 1) << 3) + lr;  // + mt*16
    const int acol = (q >> 1) << 4;
    const int brow = wn * 64 + ((q >> 1) << 3) + lr; // + p*16
    const int bcol = (q & 1) << 4;

    load_chunk(0);
    __syncthreads();
    for (int kc = 0; kc < CDIM / KCH; kc++) {
        if (kc + 1 < CDIM / KCH) load_chunk(kc + 1);
        const uint32_t abase = sb + (kc & 1) * 32768;
        const uint32_t bbase = abase + 16384;
#pragma unroll
        for (int k16 = 0; k16 < 4; k16++) {
            const int kb = k16 * 32;
            uint32_t afr[2][4], bfr[4][4];
#pragma unroll
            for (int mt = 0; mt < 2; mt++)
                ldsm4(afr[mt], abase + SW128((arow + mt * 16) * 128 + kb + acol));
#pragma unroll
            for (int p = 0; p < 4; p++)
                ldsm4(bfr[p], bbase + SW128((brow + p * 16) * 128 + kb + bcol));
#pragma unroll
            for (int mt = 0; mt < 2; mt++)
#pragma unroll
                for (int ni = 0; ni < 8; ni++)
                    mma16816(acc[mt][ni], afr[mt],
                             bfr[ni >> 1][(ni & 1) * 2], bfr[ni >> 1][(ni & 1) * 2 + 1]);
        }
        __syncthreads();
    }

    // Dump dots to smem (reuses buffer region; compute fully drained by sync).
    float* D = (float*)sm;
    {
        const int g = lane >> 2, tg = lane & 3;
#pragma unroll
        for (int mt = 0; mt < 2; mt++) {
            int r0 = wm * 32 + mt * 16 + g;
#pragma unroll
            for (int ni = 0; ni < 8; ni++) {
                int c = wn * 64 + ni * 8 + tg * 2;
                D[r0 * 133 + c]           = acc[mt][ni][0];
                D[r0 * 133 + c + 1]       = acc[mt][ni][1];
                D[(r0 + 8) * 133 + c]     = acc[mt][ni][2];
                D[(r0 + 8) * 133 + c + 1] = acc[mt][ni][3];
            }
        }
    }
    __syncthreads();

    if (tid < MT) {
        const int v = m0 + tid;
        const float szr = g_sz[v];
        const float* ses = (const float*)(sm + OFF_SE);
        float* cd = (float*)(sm + OFF_CD) + tid * 4;
        int*   ci = (int*)(sm + OFF_CI) + tid * 4;
        float runmin = 3.4e38f;
        int cnt = 0;
        for (int j = 0; j < NSLICE; j++) {
            float d = fmaf(-2.0f, D[tid * 133 + j], szr + ses[j]);
            if (d < runmin + MARGIN) {
                runmin = fminf(runmin, d);
                if (cnt < 4) { cd[cnt] = d; ci[cnt] = n0 + j; cnt++; }
                else if (cnt == 4) {
                    int w = 0;
#pragma unroll
                    for (int t = 0; t < 4; t++)
                        if (cd[t] < runmin + MARGIN) { cd[w] = cd[t]; ci[w] = ci[t]; w++; }
                    cnt = w;
                    if (cnt < 4) { cd[cnt] = d; ci[cnt] = n0 + j; cnt++; }
                    else cnt = 5;  // overflow sentinel
                }
            }
        }
        const int o = v * NSL + blockIdx.y;
        g_hmin[o] = runmin;
        g_hcnt[o] = cnt;
        int kc2 = cnt < 4 ? cnt : 4;
        for (int t = 0; t < kc2; t++) { g_hd[o * 4 + t] = cd[t]; g_hi[o * 4 + t] = ci[t]; }
    }
}

// ---------------------------------------------------------------------------
// Merge slices: unique candidate -> done; else enqueue for exact rescore.
// ---------------------------------------------------------------------------
__global__ void merge_kernel() {
    int v = blockIdx.x * blockDim.x + threadIdx.x;
    float gmin = 3.4e38f;
#pragma unroll
    for (int h = 0; h < NSL; h++) gmin = fminf(gmin, g_hmin[v * NSL + h]);
    int ucnt = 0, uidx = 0;
    bool ovf = false;
#pragma unroll
    for (int h = 0; h < NSL; h++) {
        int cnt = g_hcnt[v * NSL + h];
        if (cnt > 4) { ovf = true; continue; }
        for (int s = 0; s < cnt; s++) {
            if (g_hd[(v * NSL + h) * 4 + s] < gmin + MARGIN) {
                ucnt++;
                uidx = g_hi[(v * NSL + h) * 4 + s];
            }
        }
    }
    if (!ovf && ucnt == 1) {
        g_idx[v] = uidx;
    } else {
        int p = atomicAdd(&g_wl_cnt, 1);
        g_wl[p] = v | (ovf ? 0x80000000 : 0);
    }
}

// ---------------------------------------------------------------------------
// Exact rescore (bitwise reference recipe) for ambiguous rows. Warp per row.
// ---------------------------------------------------------------------------
__global__ void rescore_kernel(const float* __restrict__ cb) {
    __shared__ float zrow[8][256];
    int wid = threadIdx.x >> 5, lane = threadIdx.x & 31;
    int gw = blockIdx.x * 8 + wid;
    if (gw >= g_wl_cnt) return;
    int e = g_wl[gw];
    int v = e & 0x7fffffff;
    bool ovf = (e < 0);
    float* zs = zrow[wid];
#pragma unroll
    for (int t = 0; t < 8; t++) zs[lane + 32 * t] = g_zt[(size_t)v * CDIM + lane + 32 * t];
    __syncwarp();
    float sz = g_sz[v];
    float bd = __int_as_float(0x7f800000);
    int bi = 0x7fffffff;
    if (!ovf) {
        float gmin = 3.4e38f;
#pragma unroll
        for (int h = 0; h < NSL; h++) gmin = fminf(gmin, g_hmin[v * NSL + h]);
        int h = lane >> 2, s = lane & 3;  // 8 slices x 4 slots = 32 lanes
        int cnt = g_hcnt[v * NSL + h];
        if (s < cnt && g_hd[(v * NSL + h) * 4 + s] < gmin + MARGIN) {
            int idx = g_hi[(v * NSL + h) * 4 + s];
            const float* er = cb + idx * CDIM;
            float acc = 0.0f;
            for (int k = 0; k < CDIM; k++) acc = __fmaf_rn(zs[k], er[k], acc);
            bd = __fsub_rn(__fadd_rn(sz, g_se[idx]), __fmul_rn(2.0f, acc));
            bi = idx;
        }
    } else {
        for (int c = lane; c < KCODES; c += 32) {
            const float* er = cb + c * CDIM;
            float acc = 0.0f;
            for (int k = 0; k < CDIM; k++) acc = __fmaf_rn(zs[k], er[k], acc);
            float d = __fsub_rn(__fadd_rn(sz, g_se[c]), __fmul_rn(2.0f, acc));
            if (d < bd) { bd = d; bi = c; }  // ascending c: strict < keeps lowest
        }
    }
#pragma unroll
    for (int o = 16; o > 0; o >>= 1) {
        float od = __shfl_xor_sync(0xffffffffu, bd, o);
        int   oi = __shfl_xor_sync(0xffffffffu, bi, o);
        if (od < bd || (od == bd && oi < bi)) { bd = od; bi = oi; }
    }
    if (lane == 0) g_idx[v] = bi;
}

// ---------------------------------------------------------------------------
// Gather + straight-through + loss (+ indices).
// ---------------------------------------------------------------------------
__global__ void gather_kernel(const float* __restrict__ z,
                              const float* __restrict__ cb,
                              float* __restrict__ out, int mode) {
    int v  = blockIdx.x * blockDim.x + threadIdx.x;
    int b  = v >> 12, hw = v & (HWN - 1);
    int idx = g_idx[v];
    const float4* crow = (const float4*)(cb + idx * CDIM);
    float lsum = 0.0f;
    for (int cc = 0; cc < CDIM / 8; cc++) {
        float4 e0 = crow[cc * 2];
        float4 e1 = crow[cc * 2 + 1];
        float er[8] = {e0.x, e0.y, e0.z, e0.w, e1.x, e1.y, e1.z, e1.w};
#pragma unroll
        for (int j = 0; j < 8; j++) {
            int c = cc * 8 + j;
            size_t zi = (((size_t)b * CDIM + c) << 12) + hw;
            float zv = z[zi];
            float t  = __fsub_rn(er[j], zv);
            out[zi]  = __fadd_rn(zv, t);
            lsum = __fmaf_rn(t, t, lsum);
        }
    }
    for (int o = 16; o > 0; o >>= 1)
        lsum += __shfl_down_sync(0xffffffffu, lsum, o);
    if ((threadIdx.x & 31) == 0) atomicAdd(&g_loss, (double)lsum);
    if (mode >= 2) out[N_ZQ + 2 + v] = (float)idx;
}

__global__ void finalize_kernel(float* __restrict__ out, int mode) {
    if (mode >= 1) {
        float mean = (float)(g_loss / (double)N_ZQ);
        out[N_ZQ]     = mean;
        out[N_ZQ + 1] = 0.25f * mean;
    }
}

// ---------------------------------------------------------------------------
extern "C" void kernel_launch(void* const* d_in, const int* in_sizes, int n_in,
                              void* d_out, int out_size) {
    const float* z  = (const float*)d_in[0];
    const float* cb = (const float*)d_in[1];
    float* out = (float*)d_out;

    int mode = 0;
    if (out_size >= N_ZQ + 2) mode = 1;
    if (out_size >= N_ZQ + 2 + N_VEC) mode = 2;

    cudaFuncSetAttribute(vq_gemm_kernel,
                         cudaFuncAttributeMaxDynamicSharedMemorySize, SMEM_TOT);

    cb_prep_kernel<<<KCODES, 256>>>(cb);
    zprep_kernel<<<dim3(HWN / 128, CDIM / 64, NB), 256>>>(z);
    sz_kernel<<<N_VEC / 256, 256>>>(z);
    vq_gemm_kernel<<<dim3(N_VEC / MT, NSL), 256, SMEM_TOT>>>();
    merge_kernel<<<N_VEC / 256, 256>>>();
    rescore_kernel<<<N_VEC / 8, 256>>>(cb);
    gather_kernel<<<N_VEC / 256, 256>>>(z, cb, out, mode);
    finalize_kernel<<<1, 1>>>(out, mode);
}

// round 6
// speedup vs baseline: 1.6444x; 1.6444x over previous
#include <cuda_runtime.h>
#include <cuda_fp16.h>
#include <cstdint>

// Problem constants
#define NB      32
#define CDIM    256
#define HWN     4096
#define KCODES  1024
#define N_VEC   (NB * HWN)        // 131072
#define N_ZQ    (NB * CDIM * HWN) // 33554432

#define MARGIN  2.0e-3f           // ~10x worst-case |d_fast - d_ref| (f16 dot + fp32 bucket)

#define MT     128                // vectors per CTA
#define NSLICE 128                // codes per slice
#define NSL    (KCODES / NSLICE)  // 8 slices, all handled by the same CTA

// ---------------- static device scratch ----------------
__device__ __half g_zh[(size_t)N_VEC * CDIM];  // f16 z, [vec][dim]
__device__ float  g_zt[(size_t)N_VEC * CDIM];  // fp32 z, [vec][dim] (for exact rescore)
__device__ __half g_eh[KCODES * CDIM];         // f16 codebook [code][dim]
__device__ float  g_se[KCODES];                // ||e||^2
__device__ float  g_sz[N_VEC];                 // ||z||^2 (ref order)
__device__ float  g_cd[N_VEC * 4];             // compacted candidate dists
__device__ int    g_ci[N_VEC * 4];             // compacted candidate indices
__device__ int    g_ccnt[N_VEC];
__device__ int    g_idx[N_VEC];
__device__ int    g_wl[N_VEC];
__device__ int    g_wl_cnt;
__device__ double g_loss;

// ---------------- helpers ----------------
__device__ __forceinline__ uint32_t smem_u32(const void* p) {
    uint32_t a;
    asm("{ .reg .u64 t; cvta.to.shared.u64 t, %1; cvt.u32.u64 %0, t; }"
        : "=r"(a) : "l"(p));
    return a;
}
#define SW128(x) ((uint32_t)(x) ^ ((((uint32_t)(x)) >> 3) & 0x70u))

__device__ __forceinline__ void ldsm4(uint32_t* r, uint32_t addr) {
    asm volatile("ldmatrix.sync.aligned.m8n8.x4.shared.b16 {%0,%1,%2,%3}, [%4];"
                 : "=r"(r[0]), "=r"(r[1]), "=r"(r[2]), "=r"(r[3]) : "r"(addr));
}
__device__ __forceinline__ void mma16816(float* c, const uint32_t* a,
                                         uint32_t b0, uint32_t b1) {
    asm volatile("mma.sync.aligned.m16n8k16.row.col.f32.f16.f16.f32 "
                 "{%0,%1,%2,%3}, {%4,%5,%6,%7}, {%8,%9}, {%0,%1,%2,%3};"
                 : "+f"(c[0]), "+f"(c[1]), "+f"(c[2]), "+f"(c[3])
                 : "r"(a[0]), "r"(a[1]), "r"(a[2]), "r"(a[3]), "r"(b0), "r"(b1));
}

// ---------------------------------------------------------------------------
// Codebook prep: f16 copy, ||e||^2, zero global accumulators.
// ---------------------------------------------------------------------------
__global__ void cb_prep_kernel(const float* __restrict__ cb) {
    int n = blockIdx.x, t = threadIdx.x;
    float v = cb[n * CDIM + t];
    g_eh[n * CDIM + t] = __float2half(v);
    __shared__ float red[256];
    red[t] = __fmul_rn(v, v);
    __syncthreads();
    for (int s = 128; s > 0; s >>= 1) {
        if (t < s) red[t] = __fadd_rn(red[t], red[t + s]);
        __syncthreads();
    }
    if (t == 0) {
        g_se[n] = red[0];
        if (n == 0) { g_loss = 0.0; g_wl_cnt = 0; }
    }
}

// ---------------------------------------------------------------------------
// z prep: transpose [B,C,HW] -> [vec][dim] in f16 (zh) + fp32 (zt).
// ---------------------------------------------------------------------------
__global__ void zprep_kernel(const float* __restrict__ z) {
    __shared__ float t[64][133];
    int tid = threadIdx.x;
    int b = blockIdx.z, c0 = blockIdx.y * 64, hw0 = blockIdx.x * 128;
    const float* src = z + ((size_t)b * CDIM + c0) * HWN + hw0;
#pragma unroll
    for (int it = 0; it < 32; it++) {
        int idx = it * 256 + tid;
        int cc = idx >> 7, h = idx & 127;
        t[cc][h] = src[(size_t)cc * HWN + h];
    }
    __syncthreads();
#pragma unroll
    for (int it = 0; it < 32; it++) {
        int idx = it * 256 + tid;
        int h = idx >> 6, cc = idx & 63;
        size_t o = (size_t)(b * HWN + hw0 + h) * CDIM + c0 + cc;
        float val = t[cc][h];
        g_zt[o] = val;
        g_zh[o] = __float2half(val);
    }
}

// ---------------------------------------------------------------------------
// ||z||^2 in reference order (serial ascending, unfused).
// ---------------------------------------------------------------------------
__global__ void sz_kernel(const float* __restrict__ z) {
    int v  = blockIdx.x * blockDim.x + threadIdx.x;
    int b  = v >> 12, hw = v & (HWN - 1);
    const float* p = z + (size_t)b * CDIM * HWN + hw;
    float acc = 0.0f;
#pragma unroll 8
    for (int c = 0; c < CDIM; c++) {
        float x = __ldg(p + (size_t)c * HWN);
        acc = __fadd_rn(acc, __fmul_rn(x, x));
    }
    g_sz[v] = acc;
}

// ---------------------------------------------------------------------------
// Main kernel: one CTA handles 128 vectors x ALL 1024 codes.
// 512 threads, 16 warps (4m x 4n), warp tile 32x32, HMMA m16n8k16.
// z tile resident in smem; B slices streamed; per-slice dist scan with
// persistent online min + margin-candidate state; in-CTA resolution.
// ---------------------------------------------------------------------------
#define SM_ZA 0          // 65536 : z tile, 4 chunks [128 x 64dims] SW128
#define SM_B  65536      // 65536 : B slice, 4 chunks [128 x 64dims] SW128
#define SM_D  131072     // 68096 : dists 128 x 133 fp32
#define SM_SE 199168     // 4096  : ||e||^2 all 1024
#define SM_CD 203264     // 2048  : candidate dists (128 rows x 4)
#define SM_CI 205312     // 2048  : candidate indices
#define SM_TOT 207360

__global__ void __launch_bounds__(512, 1)
vq_main_kernel() {
    extern __shared__ __align__(1024) char sm[];
    const uint32_t sb = smem_u32(sm);
    const int tid = threadIdx.x;
    const int wid = tid >> 5, lane = tid & 31;
    const int wm = wid >> 2, wn = wid & 3;
    const int m0 = blockIdx.x * MT;

    // se: all 1024
    for (int i = tid; i < KCODES; i += 512)
        ((float*)(sm + SM_SE))[i] = g_se[i];

    // z tile: 4 chunks of [128 rows x 64 dims] f16, SW128 per chunk
    for (int idx = tid; idx < 4096; idx += 512) {
        int chunk = idx >> 10, w = idx & 1023;
        int r = w >> 3, c8 = w & 7;
        uint4 v = *(const uint4*)(g_zh + (size_t)(m0 + r) * CDIM + chunk * 64 + c8 * 8);
        *(uint4*)(sm + SM_ZA + chunk * 16384 + SW128(r * 128 + c8 * 16)) = v;
    }
    // B slice 0
    for (int idx = tid; idx < 4096; idx += 512) {
        int chunk = idx >> 10, w = idx & 1023;
        int r = w >> 3, c8 = w & 7;
        uint4 v = *(const uint4*)(g_eh + (size_t)r * CDIM + chunk * 64 + c8 * 8);
        *(uint4*)(sm + SM_B + chunk * 16384 + SW128(r * 128 + c8 * 16)) = v;
    }

    // persistent per-row scan state (threads 0..127)
    float szr = 0.0f, runmin = 3.4e38f;
    int cnt = 0;
    if (tid < MT) szr = g_sz[m0 + tid];
    float* cd = (float*)(sm + SM_CD) + tid * 4;
    int*   ci = (int*)(sm + SM_CI) + tid * 4;

    const int q = lane >> 3, lr = lane & 7;
    const int arow = wm * 32 + ((q & 1) << 3) + lr;
    const int acol = (q >> 1) << 4;
    const int brow = wn * 32 + ((q >> 1) << 3) + lr;
    const int bcol = (q & 1) << 4;

    __syncthreads();

    for (int ns = 0; ns < NSL; ns++) {
        float acc[2][4][4];
#pragma unroll
        for (int a = 0; a < 2; a++)
#pragma unroll
            for (int b = 0; b < 4; b++)
#pragma unroll
                for (int c = 0; c < 4; c++) acc[a][b][c] = 0.0f;

#pragma unroll
        for (int k16 = 0; k16 < 16; k16++) {
            const uint32_t abase = sb + SM_ZA + (k16 >> 2) * 16384;
            const uint32_t bbase = sb + SM_B  + (k16 >> 2) * 16384;
            const int kb = (k16 & 3) * 32;
            uint32_t afr[2][4], bfr[2][4];
            ldsm4(afr[0], abase + SW128(arow * 128 + kb + acol));
            ldsm4(afr[1], abase + SW128((arow + 16) * 128 + kb + acol));
            ldsm4(bfr[0], bbase + SW128(brow * 128 + kb + bcol));
            ldsm4(bfr[1], bbase + SW128((brow + 16) * 128 + kb + bcol));
#pragma unroll
            for (int mt = 0; mt < 2; mt++)
#pragma unroll
                for (int ni = 0; ni < 4; ni++)
                    mma16816(acc[mt][ni], afr[mt],
                             bfr[ni >> 1][(ni & 1) * 2], bfr[ni >> 1][(ni & 1) * 2 + 1]);
        }
        __syncthreads();

        // dump dists to smem (row-major, pad 133 -> conflict-free row scan)
        float* D = (float*)(sm + SM_D);
        {
            const int g = lane >> 2, tg = lane & 3;
#pragma unroll
            for (int mt = 0; mt < 2; mt++) {
                int r0 = wm * 32 + mt * 16 + g;
#pragma unroll
                for (int ni = 0; ni < 4; ni++) {
                    int c = wn * 32 + ni * 8 + tg * 2;
                    D[r0 * 133 + c]           = acc[mt][ni][0];
                    D[r0 * 133 + c + 1]       = acc[mt][ni][1];
                    D[(r0 + 8) * 133 + c]     = acc[mt][ni][2];
                    D[(r0 + 8) * 133 + c + 1] = acc[mt][ni][3];
                }
            }
        }
        __syncthreads();

        if (tid < MT) {
            // scan this slice; state persists across slices
            const float* ses = (const float*)(sm + SM_SE) + ns * NSLICE;
            const int n0 = ns * NSLICE;
            for (int j = 0; j < NSLICE; j++) {
                float d = fmaf(-2.0f, D[tid * 133 + j], szr + ses[j]);
                if (d < runmin + MARGIN) {
                    runmin = fminf(runmin, d);
                    if (cnt < 4) { cd[cnt] = d; ci[cnt] = n0 + j; cnt++; }
                    else if (cnt == 4) {
                        int w = 0;
#pragma unroll
                        for (int t = 0; t < 4; t++)
                            if (cd[t] < runmin + MARGIN) { cd[w] = cd[t]; ci[w] = ci[t]; w++; }
                        cnt = w;
                        if (cnt < 4) { cd[cnt] = d; ci[cnt] = n0 + j; cnt++; }
                        else cnt = 5;  // overflow sentinel
                    }
                }
            }
        } else if (ns + 1 < NSL) {
            // other 384 threads prefetch next B slice (MMAs for ns are done)
            for (int idx = tid - MT; idx < 4096; idx += 384) {
                int chunk = idx >> 10, w = idx & 1023;
                int r = w >> 3, c8 = w & 7;
                uint4 v = *(const uint4*)(g_eh +
                    (size_t)((ns + 1) * NSLICE + r) * CDIM + chunk * 64 + c8 * 8);
                *(uint4*)(sm + SM_B + chunk * 16384 + SW128(r * 128 + c8 * 16)) = v;
            }
        }
        __syncthreads();
    }

    // resolve: unique candidate -> done; else compact + worklist
    if (tid < MT) {
        int v = m0 + tid;
        if (cnt <= 4) {
            int u = 0, uidx = 0;
            float fcd[4]; int fci[4];
            for (int t = 0; t < cnt; t++)
                if (cd[t] < runmin + MARGIN) { fcd[u] = cd[t]; fci[u] = ci[t]; u++; uidx = ci[t]; }
            if (u == 1) {
                g_idx[v] = uidx;
            } else {
                g_ccnt[v] = u;
                for (int t = 0; t < u; t++) { g_cd[v * 4 + t] = fcd[t]; g_ci[v * 4 + t] = fci[t]; }
                int p = atomicAdd(&g_wl_cnt, 1);
                g_wl[p] = v;
            }
        } else {
            int p = atomicAdd(&g_wl_cnt, 1);
            g_wl[p] = v | 0x80000000;  // overflow: full exact rescan
        }
    }
}

// ---------------------------------------------------------------------------
// Exact rescore (bitwise reference recipe) for ambiguous rows. Warp per row.
// ---------------------------------------------------------------------------
__global__ void rescore_kernel(const float* __restrict__ cb) {
    __shared__ float zrow[8][256];
    int wid = threadIdx.x >> 5, lane = threadIdx.x & 31;
    int gw = blockIdx.x * 8 + wid;
    if (gw >= g_wl_cnt) return;
    int e = g_wl[gw];
    int v = e & 0x7fffffff;
    bool ovf = (e < 0);
    float* zs = zrow[wid];
#pragma unroll
    for (int t = 0; t < 8; t++) zs[lane + 32 * t] = g_zt[(size_t)v * CDIM + lane + 32 * t];
    __syncwarp();
    float sz = g_sz[v];
    float bd = __int_as_float(0x7f800000);
    int bi = 0x7fffffff;
    if (!ovf) {
        int cnt = g_ccnt[v];
        if (lane < cnt) {
            int idx = g_ci[v * 4 + lane];
            const float* er = cb + idx * CDIM;
            float acc = 0.0f;
            for (int k = 0; k < CDIM; k++) acc = __fmaf_rn(zs[k], er[k], acc);
            bd = __fsub_rn(__fadd_rn(sz, g_se[idx]), __fmul_rn(2.0f, acc));
            bi = idx;
        }
    } else {
        for (int c = lane; c < KCODES; c += 32) {
            const float* er = cb + c * CDIM;
            float acc = 0.0f;
            for (int k = 0; k < CDIM; k++) acc = __fmaf_rn(zs[k], er[k], acc);
            float d = __fsub_rn(__fadd_rn(sz, g_se[c]), __fmul_rn(2.0f, acc));
            if (d < bd) { bd = d; bi = c; }  // ascending c: strict < keeps lowest
        }
    }
#pragma unroll
    for (int o = 16; o > 0; o >>= 1) {
        float od = __shfl_xor_sync(0xffffffffu, bd, o);
        int   oi = __shfl_xor_sync(0xffffffffu, bi, o);
        if (od < bd || (od == bd && oi < bi)) { bd = od; bi = oi; }
    }
    if (lane == 0) g_idx[v] = bi;
}

// ---------------------------------------------------------------------------
// Gather + straight-through + loss (+ indices).
// ---------------------------------------------------------------------------
__global__ void gather_kernel(const float* __restrict__ z,
                              const float* __restrict__ cb,
                              float* __restrict__ out, int mode) {
    int v  = blockIdx.x * blockDim.x + threadIdx.x;
    int b  = v >> 12, hw = v & (HWN - 1);
    int idx = g_idx[v];
    const float4* crow = (const float4*)(cb + idx * CDIM);
    float lsum = 0.0f;
    for (int cc = 0; cc < CDIM / 8; cc++) {
        float4 e0 = crow[cc * 2];
        float4 e1 = crow[cc * 2 + 1];
        float er[8] = {e0.x, e0.y, e0.z, e0.w, e1.x, e1.y, e1.z, e1.w};
#pragma unroll
        for (int j = 0; j < 8; j++) {
            int c = cc * 8 + j;
            size_t zi = (((size_t)b * CDIM + c) << 12) + hw;
            float zv = z[zi];
            float t  = __fsub_rn(er[j], zv);
            out[zi]  = __fadd_rn(zv, t);
            lsum = __fmaf_rn(t, t, lsum);
        }
    }
    for (int o = 16; o > 0; o >>= 1)
        lsum += __shfl_down_sync(0xffffffffu, lsum, o);
    if ((threadIdx.x & 31) == 0) atomicAdd(&g_loss, (double)lsum);
    if (mode >= 2) out[N_ZQ + 2 + v] = (float)idx;
}

__global__ void finalize_kernel(float* __restrict__ out, int mode) {
    if (mode >= 1) {
        float mean = (float)(g_loss / (double)N_ZQ);
        out[N_ZQ]     = mean;
        out[N_ZQ + 1] = 0.25f * mean;
    }
}

// ---------------------------------------------------------------------------
extern "C" void kernel_launch(void* const* d_in, const int* in_sizes, int n_in,
                              void* d_out, int out_size) {
    const float* z  = (const float*)d_in[0];
    const float* cb = (const float*)d_in[1];
    float* out = (float*)d_out;

    int mode = 0;
    if (out_size >= N_ZQ + 2) mode = 1;
    if (out_size >= N_ZQ + 2 + N_VEC) mode = 2;

    cudaFuncSetAttribute(vq_main_kernel,
                         cudaFuncAttributeMaxDynamicSharedMemorySize, SM_TOT);

    cb_prep_kernel<<<KCODES, 256>>>(cb);
    zprep_kernel<<<dim3(HWN / 128, CDIM / 64, NB), 256>>>(z);
    sz_kernel<<<N_VEC / 256, 256>>>(z);
    vq_main_kernel<<<N_VEC / MT, 512, SM_TOT>>>();
    rescore_kernel<<<N_VEC / 8, 256>>>(cb);
    gather_kernel<<<N_VEC / 256, 256>>>(z, cb, out, mode);
    finalize_kernel<<<1, 1>>>(out, mode);
}